// round 4
// baseline (speedup 1.0000x reference)
#include <cuda_runtime.h>

#define NB 512
#define NT 128
#define NH 8
#define NL 3
#define LOG2E 1.4426950408889634f

#define O_WK  0
#define O_WQ  24
#define O_WV  48
#define O_WP  72
#define O_BP  96
#define O_W1  99
#define O_B1  111
#define O_W2  123
#define O_B2  135
#define O_WLM 138
#define O_BLM 139
#define NWTS  140

__device__ __forceinline__ float ex2(float x) {
    float y;
    asm("ex2.approx.ftz.f32 %0, %1;" : "=f"(y) : "f"(x));
    return y;
}

struct OS { float m, d, n; };
__device__ __forceinline__ OS comb(OS a, OS b) {
    float mx = fmaxf(a.m, b.m);
    float mn = fminf(a.m, b.m);
    float e  = ex2(mn - mx);
    bool  bl = a.m < b.m;
    float sa = bl ? e : 1.0f;
    float sb = bl ? 1.0f : e;
    OS r;
    r.m = mx;
    r.d = fmaf(a.d, sa, b.d * sb);
    r.n = fmaf(a.n, sa, b.n * sb);
    return r;
}

__global__ __launch_bounds__(256) void cat_kernel(
    const float* __restrict__ X,
    const float* __restrict__ wk, const float* __restrict__ wq, const float* __restrict__ wv,
    const float* __restrict__ Wp, const float* __restrict__ bp,
    const float* __restrict__ W1, const float* __restrict__ b1,
    const float* __restrict__ W2, const float* __restrict__ b2,
    const float* __restrict__ w_lm, const float* __restrict__ b_lm,
    float* __restrict__ out)
{
    __shared__ float xs[NT];
    __shared__ float ho[NH][NT];
    __shared__ float W[NWTS];

    const int b   = blockIdx.x;
    const int tid = threadIdx.x;
    const int h   = tid >> 5;
    const int lid = tid & 31;

    {
        int i = tid;
        if      (i < 24)  W[i] = wk[i];
        else if (i < 48)  W[i] = wq[i - 24];
        else if (i < 72)  W[i] = wv[i - 48];
        else if (i < 96)  W[i] = Wp[i - 72];
        else if (i < 99)  W[i] = bp[i - 96];
        else if (i < 111) W[i] = W1[i - 99];
        else if (i < 123) W[i] = b1[i - 111];
        else if (i < 135) W[i] = W2[i - 123];
        else if (i < 138) W[i] = b2[i - 135];
        else if (i == 138) W[i] = w_lm[0];
        else if (i == 139) W[i] = b_lm[0];
    }
    if (tid < NT) xs[tid] = X[b * NT + tid];
    __syncthreads();

    float cl0 = W[O_WK + 0*NH + h] * W[O_WQ + 0*NH + h] * LOG2E;
    float cl1 = W[O_WK + 1*NH + h] * W[O_WQ + 1*NH + h] * LOG2E;
    float cl2 = W[O_WK + 2*NH + h] * W[O_WQ + 2*NH + h] * LOG2E;
    float wv0 = W[O_WV + 0*NH + h];
    float wv1 = W[O_WV + 1*NH + h];
    float wv2 = W[O_WV + 2*NH + h];

    #pragma unroll
    for (int l = 0; l < NL; ++l) {
        const float c   = (l == 0) ? cl0 : (l == 1) ? cl1 : cl2;
        const float wvh = (l == 0) ? wv0 : (l == 1) ? wv1 : wv2;
        const int   t0  = lid * 4;

        float4 xv = reinterpret_cast<const float4*>(xs)[lid];
        float s0 = c * xv.x * xv.x;
        float s1 = c * xv.y * xv.y;
        float s2 = c * xv.z * xv.z;
        float s3 = c * xv.w * xv.w;
        float v0 = wvh * xv.x, v1 = wvh * xv.y, v2 = wvh * xv.z, v3 = wvh * xv.w;

        // warp max & min of scores (min rides in parallel, no extra depth)
        float mx = fmaxf(fmaxf(s0, s1), fmaxf(s2, s3));
        float mn = fminf(fminf(s0, s1), fminf(s2, s3));
        #pragma unroll
        for (int ofs = 16; ofs > 0; ofs >>= 1) {
            mx = fmaxf(mx, __shfl_xor_sync(0xffffffffu, mx, ofs));
            mn = fminf(mn, __shfl_xor_sync(0xffffffffu, mn, ofs));
        }

        if (mx - mn < 360.0f) {
            // ---------- fast path: two-window additive scans ----------
            const float Kh = mx - 63.0f;    // hi window: terms <= 2^63
            const float Kl = mx - 252.0f;   // lo window: covers prefixes 126..378 below max

            float eh0 = ex2(s0 - Kh), eh1 = ex2(s1 - Kh), eh2 = ex2(s2 - Kh), eh3 = ex2(s3 - Kh);
            float el0 = ex2(s0 - Kl), el1 = ex2(s1 - Kl), el2 = ex2(s2 - Kl), el3 = ex2(s3 - Kl);
            float nh0 = eh0*v0, nh1 = eh1*v1, nh2 = eh2*v2, nh3 = eh3*v3;
            float nl0 = el0*v0, nl1 = el1*v1, nl2 = el2*v2, nl3 = el3*v3;

            // local inclusive sums
            float dh01 = eh0+eh1, dh012 = dh01+eh2, dhT = dh012+eh3;
            float mh01 = nh0+nh1, mh012 = mh01+nh2, mhT = mh012+nh3;
            float dl01 = el0+el1, dl012 = dl01+el2, dlT = dl012+el3;
            float ml01 = nl0+nl1, ml012 = ml01+nl2, mlT = ml012+nl3;

            // warp inclusive add-scan (4 values)
            float sdh = dhT, snh = mhT, sdl = dlT, snl = mlT;
            #pragma unroll
            for (int ofs = 1; ofs < 32; ofs <<= 1) {
                float a = __shfl_up_sync(0xffffffffu, sdh, ofs);
                float bq= __shfl_up_sync(0xffffffffu, snh, ofs);
                float cq= __shfl_up_sync(0xffffffffu, sdl, ofs);
                float dq= __shfl_up_sync(0xffffffffu, snl, ofs);
                if (lid >= ofs) { sdh += a; snh += bq; sdl += cq; snl += dq; }
            }
            float Pdh = __shfl_up_sync(0xffffffffu, sdh, 1);
            float Pnh = __shfl_up_sync(0xffffffffu, snh, 1);
            float Pdl = __shfl_up_sync(0xffffffffu, sdl, 1);
            float Pnl = __shfl_up_sync(0xffffffffu, snl, 1);
            if (lid == 0) { Pdh = 0.f; Pnh = 0.f; Pdl = 0.f; Pnl = 0.f; }

            // element-wise exclusive prefixes and select window
            {
                float dh = Pdh,        nh = Pnh;
                float dl = Pdl,        nl = Pnl;
                ho[h][t0+0] = (dh > 1e-27f) ? __fdividef(nh, dh)
                             : (dl > 0.f)   ? __fdividef(nl, dl) : 0.0f;
            }
            {
                float dh = Pdh + eh0,  nh = Pnh + nh0;
                float dl = Pdl + el0,  nl = Pnl + nl0;
                ho[h][t0+1] = (dh > 1e-27f) ? __fdividef(nh, dh)
                             : (dl > 0.f)   ? __fdividef(nl, dl) : 0.0f;
            }
            {
                float dh = Pdh + dh01, nh = Pnh + mh01;
                float dl = Pdl + dl01, nl = Pnl + ml01;
                ho[h][t0+2] = (dh > 1e-27f) ? __fdividef(nh, dh)
                             : (dl > 0.f)   ? __fdividef(nl, dl) : 0.0f;
            }
            {
                float dh = Pdh + dh012, nh = Pnh + mh012;
                float dl = Pdl + dl012, nl = Pnl + ml012;
                ho[h][t0+3] = (dh > 1e-27f) ? __fdividef(nh, dh)
                             : (dl > 0.f)   ? __fdividef(nl, dl) : 0.0f;
            }
        } else {
            // ---------- fallback: exact online-softmax monoid scan ----------
            OS e0 = { s0, 1.0f, v0 };
            OS e1 = { s1, 1.0f, v1 };
            OS e2 = { s2, 1.0f, v2 };
            OS e3 = { s3, 1.0f, v3 };
            OS a0 = e0;
            OS a1 = comb(a0, e1);
            OS a2 = comb(a1, e2);
            OS a3 = comb(a2, e3);
            OS agg = a3;
            #pragma unroll
            for (int ofs = 1; ofs < 32; ofs <<= 1) {
                OS up;
                up.m = __shfl_up_sync(0xffffffffu, agg.m, ofs);
                up.d = __shfl_up_sync(0xffffffffu, agg.d, ofs);
                up.n = __shfl_up_sync(0xffffffffu, agg.n, ofs);
                if (lid >= ofs) agg = comb(up, agg);
            }
            OS P;
            P.m = __shfl_up_sync(0xffffffffu, agg.m, 1);
            P.d = __shfl_up_sync(0xffffffffu, agg.d, 1);
            P.n = __shfl_up_sync(0xffffffffu, agg.n, 1);
            if (lid == 0) { P.m = -1e30f; P.d = 0.0f; P.n = 0.0f; }
            OS x1e = comb(P, a0);
            OS x2e = comb(P, a1);
            OS x3e = comb(P, a2);
            ho[h][t0+0] = (P.d > 0.0f) ? __fdividef(P.n, P.d) : 0.0f;
            ho[h][t0+1] = __fdividef(x1e.n, x1e.d);
            ho[h][t0+2] = __fdividef(x2e.n, x2e.d);
            ho[h][t0+3] = __fdividef(x3e.n, x3e.d);
        }
        __syncthreads();

        if (tid < NT) {
            float y = W[O_BP + l];
            #pragma unroll
            for (int hh = 0; hh < NH; ++hh) y = fmaf(ho[hh][tid], W[O_WP + l*NH + hh], y);
            float f = W[O_B2 + l];
            #pragma unroll
            for (int k = 0; k < 4; ++k) {
                float h1 = fmaxf(fmaf(y, W[O_W1 + l*4 + k], W[O_B1 + l*4 + k]), 0.0f);
                f = fmaf(h1, W[O_W2 + l*4 + k], f);
            }
            float xn = y + f;
            if (l == NL - 1) {
                out[b * NT + tid] = fmaf(xn, W[O_WLM], W[O_BLM]);
            } else {
                xs[tid] = xn;
            }
        }
        if (l < NL - 1) __syncthreads();
    }
}

extern "C" void kernel_launch(void* const* d_in, const int* in_sizes, int n_in,
                              void* d_out, int out_size) {
    (void)in_sizes; (void)n_in; (void)out_size;
    cat_kernel<<<NB, 256>>>(
        (const float*)d_in[0],  // X
        (const float*)d_in[1],  // wk
        (const float*)d_in[2],  // wq
        (const float*)d_in[3],  // wv
        (const float*)d_in[4],  // Wp
        (const float*)d_in[5],  // bp
        (const float*)d_in[6],  // W1
        (const float*)d_in[7],  // b1
        (const float*)d_in[8],  // W2
        (const float*)d_in[9],  // b2
        (const float*)d_in[10], // w_lm
        (const float*)d_in[11], // b_lm
        (float*)d_out);
}